// round 13
// baseline (speedup 1.0000x reference)
#include <cuda_runtime.h>
#include <cuda_bf16.h>
#include <cuda_fp16.h>
#include <cstdint>
#include <cstddef>

#define RTOT 32768
#define CINK 512
#define ETOT 640
#define ENT  320
#define DD   256

// ---------------- device scratch ----------------
__device__ __half g_x16[(size_t)RTOT * CINK];    // x single fp16
__device__ __half g_W16[ETOT * CINK];            // Wp single fp16
__device__ float  g_p[(size_t)RTOT * ETOT];      // unnormalized exp, fp32
__device__ __half g_pn16[(size_t)RTOT * ETOT];   // normalized p, single fp16
__device__ __half g_cbt16[2 * DD * ENT];         // codebook^T single fp16

// ---------------- helpers ----------------
__device__ __forceinline__ uint32_t smem_u32(const void* p) {
    uint32_t a;
    asm("{ .reg .u64 t; cvta.to.shared.u64 t, %1; cvt.u32.u64 %0, t; }" : "=r"(a) : "l"(p));
    return a;
}
#define SWZ(o) ((uint32_t)(o) ^ ((((uint32_t)(o)) >> 3) & 0x70))

#define LDMX4(d, addr) \
    asm volatile("ldmatrix.sync.aligned.m8n8.x4.shared.b16 {%0,%1,%2,%3}, [%4];" \
                 : "=r"((d)[0]), "=r"((d)[1]), "=r"((d)[2]), "=r"((d)[3]) : "r"(addr))

#define MMAF16(c, a, b0, b1) \
    asm volatile("mma.sync.aligned.m16n8k16.row.col.f32.f16.f16.f32 " \
                 "{%0,%1,%2,%3},{%4,%5,%6,%7},{%8,%9},{%0,%1,%2,%3};" \
                 : "+f"((c)[0]), "+f"((c)[1]), "+f"((c)[2]), "+f"((c)[3]) \
                 : "r"((a)[0]), "r"((a)[1]), "r"((a)[2]), "r"((a)[3]), "r"(b0), "r"(b1))

#define CP16(saddr, gptr) \
    asm volatile("cp.async.cg.shared.global [%0], [%1], 16;" :: "r"(saddr), "l"(gptr) : "memory")
#define CP_COMMIT() asm volatile("cp.async.commit_group;" ::: "memory")
#define CP_WAIT1()  asm volatile("cp.async.wait_group 1;" ::: "memory")

// Stage: A [256r x 64 fp16] = 32KB (128B rows, SW128) @0; B [128r x 64] = 16KB @32768.
#define STG 49152
static constexpr int SMEM_GEMM = 3 * STG;   // 144KB/CTA -> 1 CTA/SM

// ---- chunk: single fp16, 256x128x64 CTA tile; 8 warps (4 M x 2 N), warp tile 64x64 ----
__device__ __forceinline__ void chunk64(uint32_t base, float acc[4][8][4], int lane, int wm, int wn)
{
    const uint32_t saA = base, saB = base + 32768;
    #pragma unroll
    for (int ks = 0; ks < 4; ks++) {
        uint32_t ah[4][4];
        const uint32_t kb = ks * 32 + (lane >> 4) * 16;
        #pragma unroll
        for (int mf = 0; mf < 4; mf++) {
            uint32_t rb = (wm * 64 + mf * 16 + (lane & 15)) * 128;
            LDMX4(ah[mf], saA + SWZ(rb + kb));
        }
        const uint32_t kbB = ks * 32 + ((lane >> 3) & 1) * 16;
        #pragma unroll
        for (int np = 0; np < 4; np++) {
            uint32_t rb = (wn * 64 + np * 16 + ((lane >> 4) << 3) + (lane & 7)) * 128;
            uint32_t bh[4];
            LDMX4(bh, saB + SWZ(rb + kbB));
            #pragma unroll
            for (int mf = 0; mf < 4; mf++) {
                MMAF16(acc[mf][2 * np],     ah[mf], bh[0], bh[1]);
                MMAF16(acc[mf][2 * np + 1], ah[mf], bh[2], bh[3]);
            }
        }
    }
}

// Stage loader: A 256 rows, B 128 rows, 64 K-cols (128B/row) from k0.
__device__ __forceinline__ void load64(uint32_t base, int tid,
    const __half* __restrict__ a, size_t aoff, int astr,
    const __half* __restrict__ b, size_t boff, int bstr, int k0)
{
    #pragma unroll
    for (int j = 0; j < 8; j++) {          // A: 2048 cp16
        int i = tid + j * 256;
        int r = i >> 3, c = i & 7;
        CP16(base + SWZ(r * 128 + c * 16), a + aoff + (size_t)r * astr + k0 + c * 8);
    }
    #pragma unroll
    for (int j = 0; j < 4; j++) {          // B: 1024 cp16
        int i = tid + j * 256;
        int r = i >> 3, c = i & 7;
        CP16(base + 32768 + SWZ(r * 128 + c * 16), b + boff + (size_t)r * bstr + k0 + c * 8);
    }
}

// ---------------- prep kernels ----------------
__global__ void split_x16(const float* __restrict__ x) {
    size_t i = (size_t)blockIdx.x * 256 + threadIdx.x;
    float4 v = __ldg((const float4*)x + i);
    uint32_t a = __half_as_ushort(__float2half(v.x)) | ((uint32_t)__half_as_ushort(__float2half(v.y)) << 16);
    uint32_t b = __half_as_ushort(__float2half(v.z)) | ((uint32_t)__half_as_ushort(__float2half(v.w)) << 16);
    *(uint2*)(g_x16 + i * 4) = make_uint2(a, b);
}
__global__ void split_w16(const float* __restrict__ Wp) {
    int i = blockIdx.x * 256 + threadIdx.x;
    if (i < ETOT * CINK) g_W16[i] = __float2half(__ldg(Wp + i));
}
__global__ void split_cbt16(const float* __restrict__ cb) {
    int i = blockIdx.x * 256 + threadIdx.x;   // i = (g*DD + d)*ENT + e
    if (i < 2 * DD * ENT) {
        int e = i % ENT, d = (i / ENT) % DD, g = i / (ENT * DD);
        g_cbt16[i] = __float2half(__ldg(cb + ((size_t)g * ENT + e) * DD + d));
    }
}

// ---------------- kernel 1: logits GEMM + fused exp(logit+bias+gumbel) ----------------
__global__ __launch_bounds__(256, 1) void gemm1(
    const float* __restrict__ bp, const float* __restrict__ gum)
{
    extern __shared__ char smem[];
    const uint32_t sb = smem_u32(smem);
    const int tid = threadIdx.x, lane = tid & 31, wid = tid >> 5;
    const int wm = wid & 3, wn = wid >> 2;        // 4 M-warps x 2 N-warps
    const int row0 = blockIdx.x * 256, bn0 = blockIdx.y * 128;

    float acc[4][8][4];
    #pragma unroll
    for (int i = 0; i < 4; i++)
        #pragma unroll
        for (int j = 0; j < 8; j++)
            #pragma unroll
            for (int q = 0; q < 4; q++) acc[i][j][q] = 0.f;

    const size_t aoff = (size_t)row0 * CINK, boff = (size_t)bn0 * CINK;
    load64(sb,       tid, g_x16, aoff, CINK, g_W16, boff, CINK, 0);  CP_COMMIT();
    load64(sb + STG, tid, g_x16, aoff, CINK, g_W16, boff, CINK, 64); CP_COMMIT();

    for (int kc = 0; kc < 8; kc++) {              // K chunks of 64
        CP_WAIT1();                               // group kc complete
        __syncthreads();                          // all warps done with chunk kc-1
        if (kc + 2 < 8)
            load64(sb + ((kc + 2) % 3) * STG, tid, g_x16, aoff, CINK,
                   g_W16, boff, CINK, (kc + 2) * 64);
        CP_COMMIT();                              // uniform group count
        chunk64(sb + (kc % 3) * STG, acc, lane, wm, wn);
    }

    // epilogue: p = exp(logit + bias + gumbel), store fp32
    #pragma unroll
    for (int mf = 0; mf < 4; mf++) {
        #pragma unroll
        for (int h = 0; h < 2; h++) {
            const int r = wm * 64 + mf * 16 + (lane >> 2) + h * 8;
            const size_t grow = row0 + r;
            #pragma unroll
            for (int nf = 0; nf < 8; nf++) {
                const int e = bn0 + wn * 64 + nf * 8 + (lane & 3) * 2;
                float2 gv = *(const float2*)(gum + grow * ETOT + e);
                float2 bv = *(const float2*)(bp + e);
                float2 pv;
                pv.x = __expf(acc[mf][nf][h * 2 + 0] + bv.x + gv.x);
                pv.y = __expf(acc[mf][nf][h * 2 + 1] + bv.y + gv.y);
                *(float2*)(g_p + grow * ETOT + e) = pv;
            }
        }
    }
}

// ---- zsum_norm: per-row Z from fp32 p, write normalized pn as single fp16 ----
__global__ __launch_bounds__(256) void zsum_norm() {
    const int r = blockIdx.x * 8 + (threadIdx.x >> 5);
    const int lane = threadIdx.x & 31;
    const float4* p4 = (const float4*)(g_p + (size_t)r * ETOT);
    float4 pv[5];
    float s = 0.f;
    #pragma unroll
    for (int j = 0; j < 5; j++) {
        pv[j] = __ldg(p4 + lane + j * 32);
        s += (pv[j].x + pv[j].y) + (pv[j].z + pv[j].w);
    }
    #pragma unroll
    for (int o = 16; o; o >>= 1) s += __shfl_xor_sync(0xFFFFFFFFu, s, o);
    const float rz = 1.0f / s;                 // identical in all lanes (butterfly)
    uint2* on = (uint2*)(g_pn16 + (size_t)r * ETOT);
    #pragma unroll
    for (int j = 0; j < 5; j++) {
        uint32_t a = __half_as_ushort(__float2half(pv[j].x * rz))
                   | ((uint32_t)__half_as_ushort(__float2half(pv[j].y * rz)) << 16);
        uint32_t b = __half_as_ushort(__float2half(pv[j].z * rz))
                   | ((uint32_t)__half_as_ushort(__float2half(pv[j].w * rz)) << 16);
        on[lane + j * 32] = make_uint2(a, b);
    }
}

// ---------------- kernel 2: block-diagonal codebook GEMM (normalized single-fp16 A) ----------------
__global__ __launch_bounds__(256, 1) void gemm2(float* __restrict__ out)
{
    extern __shared__ char smem[];
    const uint32_t sb = smem_u32(smem);
    const int tid = threadIdx.x, lane = tid & 31, wid = tid >> 5;
    const int wm = wid & 3, wn = wid >> 2;
    const int row0 = blockIdx.x * 256;
    const int g = blockIdx.y >> 1;
    const int d0 = (blockIdx.y & 1) * 128;
    const int oc0 = blockIdx.y * 128;

    float acc[4][8][4];
    #pragma unroll
    for (int i = 0; i < 4; i++)
        #pragma unroll
        for (int j = 0; j < 8; j++)
            #pragma unroll
            for (int q = 0; q < 4; q++) acc[i][j][q] = 0.f;

    const size_t aoff = (size_t)row0 * ETOT + (size_t)g * ENT;
    const size_t boff = (size_t)(g * DD + d0) * ENT;

    load64(sb,       tid, g_pn16, aoff, ETOT, g_cbt16, boff, ENT, 0);  CP_COMMIT();
    load64(sb + STG, tid, g_pn16, aoff, ETOT, g_cbt16, boff, ENT, 64); CP_COMMIT();

    for (int kc = 0; kc < 5; kc++) {              // 320 / 64
        CP_WAIT1();
        __syncthreads();
        if (kc + 2 < 5)
            load64(sb + ((kc + 2) % 3) * STG, tid, g_pn16, aoff, ETOT,
                   g_cbt16, boff, ENT, (kc + 2) * 64);
        CP_COMMIT();
        chunk64(sb + (kc % 3) * STG, acc, lane, wm, wn);
    }

    // epilogue: direct store (already normalized)
    #pragma unroll
    for (int mf = 0; mf < 4; mf++) {
        #pragma unroll
        for (int h = 0; h < 2; h++) {
            const int r = wm * 64 + mf * 16 + (lane >> 2) + h * 8;
            const size_t grow = row0 + r;
            #pragma unroll
            for (int nf = 0; nf < 8; nf++) {
                const int oc = oc0 + wn * 64 + nf * 8 + (lane & 3) * 2;
                float2 o;
                o.x = acc[mf][nf][h * 2 + 0];
                o.y = acc[mf][nf][h * 2 + 1];
                *(float2*)(out + grow * 512 + oc) = o;
            }
        }
    }
}

// ---------------- launch ----------------
extern "C" void kernel_launch(void* const* d_in, const int* in_sizes, int n_in,
                              void* d_out, int out_size) {
    const float* x  = (const float*)d_in[0];
    const float* Wp = (const float*)d_in[1];
    const float* bp = (const float*)d_in[2];
    const float* cb = (const float*)d_in[3];
    const float* gu = (const float*)d_in[4];
    float* out = (float*)d_out;

    cudaFuncSetAttribute(gemm1, cudaFuncAttributeMaxDynamicSharedMemorySize, SMEM_GEMM);
    cudaFuncSetAttribute(gemm2, cudaFuncAttributeMaxDynamicSharedMemorySize, SMEM_GEMM);

    split_x16<<<(RTOT * CINK / 4) / 256, 256>>>(x);
    split_w16<<<(ETOT * CINK + 255) / 256, 256>>>(Wp);
    split_cbt16<<<(2 * DD * ENT + 255) / 256, 256>>>(cb);
    gemm1<<<dim3(RTOT / 256, ETOT / 128), 256, SMEM_GEMM>>>(bp, gu);
    zsum_norm<<<RTOT / 8, 256>>>();
    gemm2<<<dim3(RTOT / 256, 4), 256, SMEM_GEMM>>>(out);
}

// round 14
// speedup vs baseline: 1.1536x; 1.1536x over previous
#include <cuda_runtime.h>
#include <cuda_bf16.h>
#include <cuda_fp16.h>
#include <cstdint>
#include <cstddef>

#define RTOT 32768
#define CINK 512
#define ETOT 640
#define ENT  320
#define DD   256

// ---------------- device scratch ----------------
__device__ __half g_x16[(size_t)RTOT * CINK];    // x single fp16
__device__ __half g_W16[ETOT * CINK];            // Wp single fp16
__device__ float  g_p[(size_t)RTOT * ETOT];      // unnormalized exp, fp32
__device__ __half g_pn16[(size_t)RTOT * ETOT];   // normalized p, single fp16
__device__ __half g_cbt16[2 * DD * ENT];         // codebook^T single fp16

// ---------------- helpers ----------------
__device__ __forceinline__ uint32_t smem_u32(const void* p) {
    uint32_t a;
    asm("{ .reg .u64 t; cvta.to.shared.u64 t, %1; cvt.u32.u64 %0, t; }" : "=r"(a) : "l"(p));
    return a;
}
#define SWZ(o)   ((uint32_t)(o) ^ ((((uint32_t)(o)) >> 3) & 0x70))
#define SWZ64(o) ((uint32_t)(o) ^ ((((uint32_t)(o)) >> 3) & 0x30))

#define LDMX4(d, addr) \
    asm volatile("ldmatrix.sync.aligned.m8n8.x4.shared.b16 {%0,%1,%2,%3}, [%4];" \
                 : "=r"((d)[0]), "=r"((d)[1]), "=r"((d)[2]), "=r"((d)[3]) : "r"(addr))

#define MMAF16(c, a, b0, b1) \
    asm volatile("mma.sync.aligned.m16n8k16.row.col.f32.f16.f16.f32 " \
                 "{%0,%1,%2,%3},{%4,%5,%6,%7},{%8,%9},{%0,%1,%2,%3};" \
                 : "+f"((c)[0]), "+f"((c)[1]), "+f"((c)[2]), "+f"((c)[3]) \
                 : "r"((a)[0]), "r"((a)[1]), "r"((a)[2]), "r"((a)[3]), "r"(b0), "r"(b1))

#define CP16(saddr, gptr) \
    asm volatile("cp.async.cg.shared.global [%0], [%1], 16;" :: "r"(saddr), "l"(gptr) : "memory")
#define CP_COMMIT() asm volatile("cp.async.commit_group;" ::: "memory")
#define CP_WAIT1()  asm volatile("cp.async.wait_group 1;" ::: "memory")

// gemm1 stage: A [128r x 64 fp16] 16KB (128B rows, SW128) @0; B same @16384. 32KB x 3.
#define STG1 32768
static constexpr int SMEM1 = 3 * STG1;     // 96KB/CTA -> 2 CTAs/SM
// gemm2 stage: A [128r x 32 fp16] 8KB (64B rows, SW64) @0; B same @8192. 16KB x 3.
#define STG2 16384
static constexpr int SMEM2 = 3 * STG2;     // 48KB/CTA

// ---- gemm1 chunk: single fp16, 128x128x64, warp tile 32x64, software-pipelined frags ----
__device__ __forceinline__ void chunk1(uint32_t base, float acc[2][8][4], int lane, int wm, int wn)
{
    const uint32_t saA = base, saB = base + 16384;
    const uint32_t arow = (wm * 32 + (lane & 15)) * 128 + (lane >> 4) * 16;
    const uint32_t brow = (wn * 64 + ((lane >> 4) << 3) + (lane & 7)) * 128 + ((lane >> 3) & 1) * 16;

    uint32_t ah[2][2][4], bh[2][4];
    LDMX4(ah[0][0], saA + SWZ(arow));
    LDMX4(ah[0][1], saA + SWZ(arow + 2048));
    LDMX4(bh[0],    saB + SWZ(brow));
    #pragma unroll
    for (int ks = 0; ks < 4; ks++) {
        const int ab = ks & 1;
        #pragma unroll
        for (int np = 0; np < 4; np++) {
            const int cb = (ks * 4 + np) & 1;
            if (np < 3) {
                LDMX4(bh[cb ^ 1], saB + SWZ(brow + (np + 1) * 2048 + ks * 32));
            } else if (ks < 3) {
                LDMX4(ah[ab ^ 1][0], saA + SWZ(arow + (ks + 1) * 32));
                LDMX4(ah[ab ^ 1][1], saA + SWZ(arow + 2048 + (ks + 1) * 32));
                LDMX4(bh[cb ^ 1],    saB + SWZ(brow + (ks + 1) * 32));
            }
            MMAF16(acc[0][2 * np],     ah[ab][0], bh[cb][0], bh[cb][1]);
            MMAF16(acc[0][2 * np + 1], ah[ab][0], bh[cb][2], bh[cb][3]);
            MMAF16(acc[1][2 * np],     ah[ab][1], bh[cb][0], bh[cb][1]);
            MMAF16(acc[1][2 * np + 1], ah[ab][1], bh[cb][2], bh[cb][3]);
        }
    }
}

// ---- gemm2 chunk: single fp16, 128x128x32, 64B rows SW64, software-pipelined frags ----
__device__ __forceinline__ void chunk2(uint32_t base, float acc[2][8][4], int lane, int wm, int wn)
{
    const uint32_t saA = base, saB = base + 8192;
    const uint32_t arow = (wm * 32 + (lane & 15)) * 64 + (lane >> 4) * 16;
    const uint32_t brow = (wn * 64 + ((lane >> 4) << 3) + (lane & 7)) * 64 + ((lane >> 3) & 1) * 16;

    uint32_t ah[2][2][4], bh[2][4];
    LDMX4(ah[0][0], saA + SWZ64(arow));
    LDMX4(ah[0][1], saA + SWZ64(arow + 1024));
    LDMX4(bh[0],    saB + SWZ64(brow));
    #pragma unroll
    for (int ks = 0; ks < 2; ks++) {
        const int ab = ks & 1;
        #pragma unroll
        for (int np = 0; np < 4; np++) {
            const int cb = (ks * 4 + np) & 1;
            if (np < 3) {
                LDMX4(bh[cb ^ 1], saB + SWZ64(brow + (np + 1) * 1024 + ks * 32));
            } else if (ks < 1) {
                LDMX4(ah[ab ^ 1][0], saA + SWZ64(arow + 32));
                LDMX4(ah[ab ^ 1][1], saA + SWZ64(arow + 1024 + 32));
                LDMX4(bh[cb ^ 1],    saB + SWZ64(brow + 32));
            }
            MMAF16(acc[0][2 * np],     ah[ab][0], bh[cb][0], bh[cb][1]);
            MMAF16(acc[0][2 * np + 1], ah[ab][0], bh[cb][2], bh[cb][3]);
            MMAF16(acc[1][2 * np],     ah[ab][1], bh[cb][0], bh[cb][1]);
            MMAF16(acc[1][2 * np + 1], ah[ab][1], bh[cb][2], bh[cb][3]);
        }
    }
}

// ---------------- prep kernels ----------------
__global__ void split_x16(const float* __restrict__ x) {
    size_t i = (size_t)blockIdx.x * 256 + threadIdx.x;
    float4 v = __ldg((const float4*)x + i);
    uint32_t a = __half_as_ushort(__float2half(v.x)) | ((uint32_t)__half_as_ushort(__float2half(v.y)) << 16);
    uint32_t b = __half_as_ushort(__float2half(v.z)) | ((uint32_t)__half_as_ushort(__float2half(v.w)) << 16);
    *(uint2*)(g_x16 + i * 4) = make_uint2(a, b);
}
__global__ void split_w16(const float* __restrict__ Wp) {
    int i = blockIdx.x * 256 + threadIdx.x;
    if (i < ETOT * CINK) g_W16[i] = __float2half(__ldg(Wp + i));
}
__global__ void split_cbt16(const float* __restrict__ cb) {
    int i = blockIdx.x * 256 + threadIdx.x;   // i = (g*DD + d)*ENT + e
    if (i < 2 * DD * ENT) {
        int e = i % ENT, d = (i / ENT) % DD, g = i / (ENT * DD);
        g_cbt16[i] = __float2half(__ldg(cb + ((size_t)g * ENT + e) * DD + d));
    }
}

// ---------------- kernel 1: logits GEMM + fused exp(logit+bias+gumbel) ----------------
__device__ __forceinline__ void g1_load(uint32_t base, int tid, int row0, int bn0, int k0) {
    #pragma unroll
    for (int j = 0; j < 4; j++) {
        int i = tid + j * 256;
        int r = i >> 3, c = i & 7;
        uint32_t dst = SWZ(r * 128 + c * 16);
        CP16(base + dst,         g_x16 + (size_t)(row0 + r) * CINK + k0 + c * 8);
        CP16(base + 16384 + dst, g_W16 + (size_t)(bn0 + r) * CINK + k0 + c * 8);
    }
}

__global__ __launch_bounds__(256, 2) void gemm1(
    const float* __restrict__ bp, const float* __restrict__ gum)
{
    extern __shared__ char smem[];
    const uint32_t sb = smem_u32(smem);
    const int tid = threadIdx.x, lane = tid & 31, wid = tid >> 5;
    const int wm = wid & 3, wn = wid >> 2;
    const int row0 = blockIdx.x * 128, bn0 = blockIdx.y * 128;

    float acc[2][8][4];
    #pragma unroll
    for (int i = 0; i < 2; i++)
        #pragma unroll
        for (int j = 0; j < 8; j++)
            #pragma unroll
            for (int q = 0; q < 4; q++) acc[i][j][q] = 0.f;

    g1_load(sb,        tid, row0, bn0, 0);  CP_COMMIT();
    g1_load(sb + STG1, tid, row0, bn0, 64); CP_COMMIT();

    for (int kc = 0; kc < 8; kc++) {          // K chunks of 64
        CP_WAIT1();                           // group kc complete (newest may pend)
        __syncthreads();                      // all warps done with chunk kc-1
        if (kc + 2 < 8)
            g1_load(sb + ((kc + 2) % 3) * STG1, tid, row0, bn0, (kc + 2) * 64);
        CP_COMMIT();                          // uniform group count
        chunk1(sb + (kc % 3) * STG1, acc, lane, wm, wn);
    }

    // epilogue: p = exp(logit + bias + gumbel), store fp32
    #pragma unroll
    for (int mf = 0; mf < 2; mf++) {
        #pragma unroll
        for (int h = 0; h < 2; h++) {
            const int r = wm * 32 + mf * 16 + (lane >> 2) + h * 8;
            const size_t grow = row0 + r;
            #pragma unroll
            for (int nf = 0; nf < 8; nf++) {
                const int e = bn0 + wn * 64 + nf * 8 + (lane & 3) * 2;
                float2 gv = *(const float2*)(gum + grow * ETOT + e);
                float2 bv = *(const float2*)(bp + e);
                float2 pv;
                pv.x = __expf(acc[mf][nf][h * 2 + 0] + bv.x + gv.x);
                pv.y = __expf(acc[mf][nf][h * 2 + 1] + bv.y + gv.y);
                *(float2*)(g_p + grow * ETOT + e) = pv;
            }
        }
    }
}

// ---- zsum_norm: per-row Z from fp32 p, write normalized pn as single fp16 ----
__global__ __launch_bounds__(256) void zsum_norm() {
    const int r = blockIdx.x * 8 + (threadIdx.x >> 5);
    const int lane = threadIdx.x & 31;
    const float4* p4 = (const float4*)(g_p + (size_t)r * ETOT);
    float4 pv[5];
    float s = 0.f;
    #pragma unroll
    for (int j = 0; j < 5; j++) {
        pv[j] = __ldg(p4 + lane + j * 32);
        s += (pv[j].x + pv[j].y) + (pv[j].z + pv[j].w);
    }
    #pragma unroll
    for (int o = 16; o; o >>= 1) s += __shfl_xor_sync(0xFFFFFFFFu, s, o);
    const float rz = 1.0f / s;                 // identical in all lanes (butterfly)
    uint2* on = (uint2*)(g_pn16 + (size_t)r * ETOT);
    #pragma unroll
    for (int j = 0; j < 5; j++) {
        uint32_t a = __half_as_ushort(__float2half(pv[j].x * rz))
                   | ((uint32_t)__half_as_ushort(__float2half(pv[j].y * rz)) << 16);
        uint32_t b = __half_as_ushort(__float2half(pv[j].z * rz))
                   | ((uint32_t)__half_as_ushort(__float2half(pv[j].w * rz)) << 16);
        on[lane + j * 32] = make_uint2(a, b);
    }
}

// ---------------- kernel 2: block-diagonal codebook GEMM (normalized single-fp16 A) ----------------
__device__ __forceinline__ void g2_load(uint32_t base, int tid, size_t aoff, size_t boff, int k0) {
    #pragma unroll
    for (int j = 0; j < 2; j++) {
        int i = tid + j * 256;
        int r = i >> 2, c = i & 3;
        uint32_t dst = SWZ64(r * 64 + c * 16);
        CP16(base + dst,        g_pn16  + aoff + (size_t)r * ETOT + k0 + c * 8);
        CP16(base + 8192 + dst, g_cbt16 + boff + (size_t)r * ENT  + k0 + c * 8);
    }
}

__global__ __launch_bounds__(256, 2) void gemm2(float* __restrict__ out)
{
    extern __shared__ char smem[];
    const uint32_t sb = smem_u32(smem);
    const int tid = threadIdx.x, lane = tid & 31, wid = tid >> 5;
    const int wm = wid & 3, wn = wid >> 2;
    const int row0 = blockIdx.x * 128;
    const int g = blockIdx.y >> 1;
    const int d0 = (blockIdx.y & 1) * 128;
    const int oc0 = blockIdx.y * 128;

    float acc[2][8][4];
    #pragma unroll
    for (int i = 0; i < 2; i++)
        #pragma unroll
        for (int j = 0; j < 8; j++)
            #pragma unroll
            for (int q = 0; q < 4; q++) acc[i][j][q] = 0.f;

    const size_t aoff = (size_t)row0 * ETOT + (size_t)g * ENT;
    const size_t boff = (size_t)(g * DD + d0) * ENT;

    g2_load(sb,        tid, aoff, boff, 0);  CP_COMMIT();
    g2_load(sb + STG2, tid, aoff, boff, 32); CP_COMMIT();

    for (int kc = 0; kc < 10; kc++) {         // K chunks of 32 over ENT=320
        CP_WAIT1();
        __syncthreads();
        if (kc + 2 < 10)
            g2_load(sb + ((kc + 2) % 3) * STG2, tid, aoff, boff, (kc + 2) * 32);
        CP_COMMIT();
        chunk2(sb + (kc % 3) * STG2, acc, lane, wm, wn);
    }

    // epilogue: direct store (already normalized)
    #pragma unroll
    for (int mf = 0; mf < 2; mf++) {
        #pragma unroll
        for (int h = 0; h < 2; h++) {
            const int r = wm * 32 + mf * 16 + (lane >> 2) + h * 8;
            const size_t grow = row0 + r;
            #pragma unroll
            for (int nf = 0; nf < 8; nf++) {
                const int oc = oc0 + wn * 64 + nf * 8 + (lane & 3) * 2;
                float2 o;
                o.x = acc[mf][nf][h * 2 + 0];
                o.y = acc[mf][nf][h * 2 + 1];
                *(float2*)(out + grow * 512 + oc) = o;
            }
        }
    }
}

// ---------------- launch ----------------
extern "C" void kernel_launch(void* const* d_in, const int* in_sizes, int n_in,
                              void* d_out, int out_size) {
    const float* x  = (const float*)d_in[0];
    const float* Wp = (const float*)d_in[1];
    const float* bp = (const float*)d_in[2];
    const float* cb = (const float*)d_in[3];
    const float* gu = (const float*)d_in[4];
    float* out = (float*)d_out;

    cudaFuncSetAttribute(gemm1, cudaFuncAttributeMaxDynamicSharedMemorySize, SMEM1);
    cudaFuncSetAttribute(gemm2, cudaFuncAttributeMaxDynamicSharedMemorySize, SMEM2);

    split_x16<<<(RTOT * CINK / 4) / 256, 256>>>(x);
    split_w16<<<(ETOT * CINK + 255) / 256, 256>>>(Wp);
    split_cbt16<<<(2 * DD * ENT + 255) / 256, 256>>>(cb);
    gemm1<<<dim3(RTOT / 128, ETOT / 128), 256, SMEM1>>>(bp, gu);
    zsum_norm<<<RTOT / 8, 256>>>();
    gemm2<<<dim3(RTOT / 128, 4), 256, SMEM2>>>(out);
}